// round 16
// baseline (speedup 1.0000x reference)
#include <cuda_runtime.h>
#include <cuda_bf16.h>
#include <cstdint>

typedef uint32_t u32;
typedef uint64_t u64;

#define BHN 256
#define NHEADS 16
#define DH 64
#define TQ 128
#define TK 128
#define THREADS 512

// ---- smem byte offsets (225 KB, 1 CTA/SM) ----
#define SM_QH 0        // Q hi 128x64 bf16 (16K), persists
#define SM_QL 16384
#define SM_GH 32768    // K@q-rows hi/lo (bias A), persists
#define SM_GL 49152
#define SM_KH 65536    // K tile hi (16K); aliased by V^T hi (64 d x 128 j) after QK
#define SM_KL 81920
#define SM_EH 98304    // E band 256 rows x 64 bf16 hi (32K)
#define SM_EL 131072
#define SM_SC 163840   // score f32 128x128 (64K); later Ph(32K)+Pl(32K)
#define SM_PH 163840
#define SM_PL 196608
#define SM_CR 229376   // corr[128] f32
#define SM_LI 229888   // linv[128] f32
#define SM_TOTAL 230400

__device__ __forceinline__ void MMA(float* c, u32 a0, u32 a1, u32 a2, u32 a3, u32 b0, u32 b1){
    asm volatile("mma.sync.aligned.m16n8k16.row.col.f32.bf16.bf16.f32 "
        "{%0,%1,%2,%3}, {%4,%5,%6,%7}, {%8,%9}, {%0,%1,%2,%3};"
        : "+f"(c[0]), "+f"(c[1]), "+f"(c[2]), "+f"(c[3])
        : "r"(a0), "r"(a1), "r"(a2), "r"(a3), "r"(b0), "r"(b1));
}

// fragment word load, 32-word rows (64 bf16)
__device__ __forceinline__ u32 ldf32w(const u32* buf, int row, int kw, int lane4){
    return buf[row*32 + ((kw + lane4) ^ ((row & 7) << 2))];
}
// fragment word load, 64-word rows (128 bf16) — P and V^T
__device__ __forceinline__ u32 ldf64w(const u32* buf, int row, int kw, int lane4){
    return buf[row*64 + ((kw + lane4) ^ ((row & 7) << 2))];
}
// score f32 word index (128-word rows, pair-swizzled)
__device__ __forceinline__ int sidx(int r, int c){
    return r*128 + 2*((c >> 1) ^ ((r & 7) << 2)) + (c & 1);
}

__device__ __forceinline__ void split2(float x0, float x1, u32 &H, u32 &L){
    __nv_bfloat162 hv = __floats2bfloat162_rn(x0, x1);
    __nv_bfloat162 lv = __floats2bfloat162_rn(x0 - __bfloat162float(hv.x),
                                              x1 - __bfloat162float(hv.y));
    H = *reinterpret_cast<u32*>(&hv);
    L = *reinterpret_cast<u32*>(&lv);
}
__device__ __forceinline__ void splitpack4(float4 a, u64 &H, u64 &L){
    u32 h0,l0,h1,l1;
    split2(a.x, a.y, h0, l0);
    split2(a.z, a.w, h1, l1);
    H = (u64)h0 | ((u64)h1 << 32);
    L = (u64)l0 | ((u64)l1 << 32);
}
__device__ __forceinline__ void st_hl(u32* bufH, u32* bufL, int row, int sg, u64 Hv, u64 Lv){
    int w = row*32 + ((2*sg) ^ ((row & 7) << 2));
    *reinterpret_cast<u64*>(bufH + w) = Hv;
    *reinterpret_cast<u64*>(bufL + w) = Lv;
}

__global__ void __launch_bounds__(THREADS, 1)
attn_mma512_kernel(const float* __restrict__ q, const float* __restrict__ k,
                   const float* __restrict__ v, const float* __restrict__ emb,
                   float* __restrict__ out)
{
    extern __shared__ char smc[];
    u32* QH = (u32*)(smc + SM_QH);  u32* QL = (u32*)(smc + SM_QL);
    u32* GH = (u32*)(smc + SM_GH);  u32* GL = (u32*)(smc + SM_GL);
    u32* KH = (u32*)(smc + SM_KH);  u32* KL = (u32*)(smc + SM_KL);   // also V^T
    u32* EH = (u32*)(smc + SM_EH);  u32* EL = (u32*)(smc + SM_EL);
    u32* PH = (u32*)(smc + SM_PH);  u32* PL = (u32*)(smc + SM_PL);
    float* SC = (float*)(smc + SM_SC);
    float* CR = (float*)(smc + SM_CR);
    float* LI = (float*)(smc + SM_LI);

    const int tid = threadIdx.x;
    const int T = tid & 31, W = tid >> 5;        // 16 warps
    const int lane4 = T & 3, g4 = T >> 2;
    const int wm  = (W >> 2) * 32;               // 4 m-groups of 32 rows
    const int wnq = (W & 3) * 32;                // QK cols (128 wide)
    const int wub = (W & 3) * 64;                // band u cols (256 wide)
    const int wnp = (W & 3) * 16;                // PV cols (64 wide)
    const int bh = blockIdx.x, h = bh & (NHEADS - 1);
    const int i0 = blockIdx.y * TQ;
    const float scale = 0.125f;

    // ---- prologue: load+split Q and K@q-rows ----
    #pragma unroll
    for (int it = 0; it < 4; it++){
        int idx = tid + THREADS*it;
        int row = idx >> 4, sg = idx & 15;
        size_t g = ((size_t)(i0 + row) * BHN + bh) * DH + sg * 4;
        float4 qa = *(const float4*)(q + g);
        float4 ka = *(const float4*)(k + g);
        u64 H, L;
        splitpack4(qa, H, L); st_hl(QH, QL, row, sg, H, L);
        splitpack4(ka, H, L); st_hl(GH, GL, row, sg, H, L);
    }

    float O[2][2][4];
    #pragma unroll
    for (int a = 0; a < 2; a++)
        #pragma unroll
        for (int b = 0; b < 2; b++)
            #pragma unroll
            for (int c = 0; c < 4; c++) O[a][b][c] = 0.f;
    float mrun = -1e30f, lrun = 0.f;

    #pragma unroll 1
    for (int t = 0; t < 4; t++){
        const int j0 = t * TK;
        __syncthreads();   // prev PV done with V^T (K alias) and P

        // ---- load K tile + full E band (256 rows, row 255 zero/guarded) ----
        #pragma unroll
        for (int it = 0; it < 4; it++){
            int idx = tid + THREADS*it;
            int row = idx >> 4, sg = idx & 15;
            size_t g = ((size_t)(j0 + row) * BHN + bh) * DH + sg * 4;
            float4 ka = *(const float4*)(k + g);
            u64 H, L; splitpack4(ka, H, L);
            st_hl(KH, KL, row, sg, H, L);
        }
        {
            int rb = j0 - i0 + 384;               // in [0,768]
            #pragma unroll
            for (int it = 0; it < 8; it++){
                int idx = tid + THREADS*it;
                int row = idx >> 4, sg = idx & 15;
                int gr = rb + row;
                u64 H = 0ull, L = 0ull;
                if (gr <= 1022){
                    float4 ea = *(const float4*)(emb + ((size_t)h*1023 + gr)*DH + sg*4);
                    splitpack4(ea, H, L);
                }
                st_hl(EH, EL, row, sg, H, L);
            }
        }
        __syncthreads();

        // ---- QK^T: 3 hi/lo splits -> SC ----
        {
            float C[2][4][4];
            #pragma unroll
            for (int a = 0; a < 2; a++)
                #pragma unroll
                for (int b = 0; b < 4; b++)
                    #pragma unroll
                    for (int c = 0; c < 4; c++) C[a][b][c] = 0.f;
            #pragma unroll
            for (int s = 0; s < 3; s++){
                const u32* Ab = (s == 2) ? QL : QH;
                const u32* Bb = (s == 1) ? KL : KH;
                #pragma unroll
                for (int ks = 0; ks < 4; ks++){
                    int kw = ks * 8;
                    u32 a[2][4];
                    #pragma unroll
                    for (int mf = 0; mf < 2; mf++){
                        int rb2 = wm + mf*16;
                        a[mf][0] = ldf32w(Ab, rb2 + g4,     kw,     lane4);
                        a[mf][1] = ldf32w(Ab, rb2 + 8 + g4, kw,     lane4);
                        a[mf][2] = ldf32w(Ab, rb2 + g4,     kw + 4, lane4);
                        a[mf][3] = ldf32w(Ab, rb2 + 8 + g4, kw + 4, lane4);
                    }
                    #pragma unroll
                    for (int nf = 0; nf < 4; nf++){
                        int nb = wnq + nf*8;
                        u32 b0 = ldf32w(Bb, nb + g4, kw,     lane4);
                        u32 b1 = ldf32w(Bb, nb + g4, kw + 4, lane4);
                        MMA(C[0][nf], a[0][0], a[0][1], a[0][2], a[0][3], b0, b1);
                        MMA(C[1][nf], a[1][0], a[1][1], a[1][2], a[1][3], b0, b1);
                    }
                }
            }
            #pragma unroll
            for (int mf = 0; mf < 2; mf++)
                #pragma unroll
                for (int nf = 0; nf < 4; nf++){
                    int r = wm + mf*16 + g4;
                    int c = wnq + nf*8 + lane4*2;
                    *reinterpret_cast<float2*>(SC + sidx(r, c))     = make_float2(C[mf][nf][0], C[mf][nf][1]);
                    *reinterpret_cast<float2*>(SC + sidx(r + 8, c)) = make_float2(C[mf][nf][2], C[mf][nf][3]);
                }
        }
        __syncthreads();   // SC complete; K tile dead

        // ---- V^T build into dead K space, then band MMAs + shear-add ----
        {
            #pragma unroll
            for (int it = 0; it < 2; it++){
                int idx = tid + THREADS*it;
                int jp = idx & 63, ds = idx >> 6;     // 64 j-pairs, 16 d-segs
                union { float4 v4; float f[4]; } A2, B2;
                A2.v4 = *(const float4*)(v + ((size_t)(j0 + 2*jp    ) * BHN + bh) * DH + 4*ds);
                B2.v4 = *(const float4*)(v + ((size_t)(j0 + 2*jp + 1) * BHN + bh) * DH + 4*ds);
                #pragma unroll
                for (int e = 0; e < 4; e++){
                    int d = 4*ds + e;
                    u32 hi, lo; split2(A2.f[e], B2.f[e], hi, lo);
                    int wv = d*64 + (jp ^ ((d & 7) << 2));
                    KH[wv] = hi; KL[wv] = lo;
                }
            }

            float C[2][8][4];
            #pragma unroll
            for (int a = 0; a < 2; a++)
                #pragma unroll
                for (int b = 0; b < 8; b++)
                    #pragma unroll
                    for (int c = 0; c < 4; c++) C[a][b][c] = 0.f;
            #pragma unroll
            for (int s = 0; s < 3; s++){
                const u32* Ab = (s == 2) ? GL : GH;
                const u32* Bb = (s == 1) ? EL : EH;
                #pragma unroll
                for (int ks = 0; ks < 4; ks++){
                    int kw = ks * 8;
                    u32 a[2][4];
                    #pragma unroll
                    for (int mf = 0; mf < 2; mf++){
                        int rb2 = wm + mf*16;
                        a[mf][0] = ldf32w(Ab, rb2 + g4,     kw,     lane4);
                        a[mf][1] = ldf32w(Ab, rb2 + 8 + g4, kw,     lane4);
                        a[mf][2] = ldf32w(Ab, rb2 + g4,     kw + 4, lane4);
                        a[mf][3] = ldf32w(Ab, rb2 + 8 + g4, kw + 4, lane4);
                    }
                    #pragma unroll
                    for (int nf = 0; nf < 8; nf++){
                        int nb = wub + nf*8;
                        u32 b0 = ldf32w(Bb, nb + g4, kw,     lane4);
                        u32 b1 = ldf32w(Bb, nb + g4, kw + 4, lane4);
                        MMA(C[0][nf], a[0][0], a[0][1], a[0][2], a[0][3], b0, b1);
                        MMA(C[1][nf], a[1][0], a[1][1], a[1][2], a[1][3], b0, b1);
                    }
                }
            }
            // shear-add: score[r][u + r - 127] += C  (bijective -> no races)
            #pragma unroll
            for (int mf = 0; mf < 2; mf++)
                #pragma unroll
                for (int nf = 0; nf < 8; nf++){
                    int r0 = wm + mf*16 + g4, r1 = r0 + 8;
                    int u  = wub + nf*8 + lane4*2;
                    int ja = u + r0 - 127;
                    int jb = u + r1 - 127;
                    if ((unsigned)ja     < 128u) SC[sidx(r0, ja)]     += C[mf][nf][0];
                    if ((unsigned)(ja+1) < 128u) SC[sidx(r0, ja + 1)] += C[mf][nf][1];
                    if ((unsigned)jb     < 128u) SC[sidx(r1, jb)]     += C[mf][nf][2];
                    if ((unsigned)(jb+1) < 128u) SC[sidx(r1, jb + 1)] += C[mf][nf][3];
                }
        }
        __syncthreads();   // scores final; V^T ready

        // ---- softmax: 4 threads/row, qt-interleaved cols (conflict-free) ----
        {
            int r = tid >> 2, qt = tid & 3;
            float sv[32];
            #pragma unroll
            for (int p = 0; p < 16; p++){
                float2 t2 = *reinterpret_cast<float2*>(
                    SC + r*128 + 2*((4*p + qt) ^ ((r & 7) << 2)));
                sv[2*p] = t2.x; sv[2*p+1] = t2.y;
            }
            float rm = sv[0];
            #pragma unroll
            for (int e = 1; e < 32; e++) rm = fmaxf(rm, sv[e]);
            rm = fmaxf(rm, __shfl_xor_sync(0xffffffffu, rm, 1));
            rm = fmaxf(rm, __shfl_xor_sync(0xffffffffu, rm, 2));
            float mn = fmaxf(mrun, rm * scale);
            float corr = __expf(mrun - mn);
            mrun = mn;
            float rs = 0.f;
            #pragma unroll
            for (int e = 0; e < 32; e++){ sv[e] = __expf(sv[e]*scale - mn); rs += sv[e]; }
            rs += __shfl_xor_sync(0xffffffffu, rs, 1);
            rs += __shfl_xor_sync(0xffffffffu, rs, 2);
            lrun = lrun * corr + rs;
            if (qt == 0) CR[r] = corr;
            __syncthreads();   // all SC reads done; safe to overwrite with P
            #pragma unroll
            for (int p = 0; p < 16; p++){
                u32 hi, lo; split2(sv[2*p], sv[2*p+1], hi, lo);
                int wv = r*64 + ((4*p + qt) ^ ((r & 7) << 2));
                PH[wv] = hi; PL[wv] = lo;
            }
        }
        __syncthreads();   // P ready

        // ---- PV: O = O*corr + P . V ----
        {
            float cr0[2], cr1[2];
            #pragma unroll
            for (int mf = 0; mf < 2; mf++){
                cr0[mf] = CR[wm + mf*16 + g4];
                cr1[mf] = CR[wm + mf*16 + 8 + g4];
            }
            #pragma unroll
            for (int mf = 0; mf < 2; mf++)
                #pragma unroll
                for (int nf = 0; nf < 2; nf++){
                    O[mf][nf][0] *= cr0[mf]; O[mf][nf][1] *= cr0[mf];
                    O[mf][nf][2] *= cr1[mf]; O[mf][nf][3] *= cr1[mf];
                }
            #pragma unroll
            for (int s = 0; s < 3; s++){
                const u32* Ab = (s == 2) ? PL : PH;
                const u32* Bb = (s == 1) ? KL : KH;   // V^T lo / hi
                #pragma unroll
                for (int ks = 0; ks < 8; ks++){
                    int kw = ks * 8;
                    u32 a[2][4];
                    #pragma unroll
                    for (int mf = 0; mf < 2; mf++){
                        int rb2 = wm + mf*16;
                        a[mf][0] = ldf64w(Ab, rb2 + g4,     kw,     lane4);
                        a[mf][1] = ldf64w(Ab, rb2 + 8 + g4, kw,     lane4);
                        a[mf][2] = ldf64w(Ab, rb2 + g4,     kw + 4, lane4);
                        a[mf][3] = ldf64w(Ab, rb2 + 8 + g4, kw + 4, lane4);
                    }
                    #pragma unroll
                    for (int nf = 0; nf < 2; nf++){
                        int nb = wnp + nf*8;
                        u32 b0 = ldf64w(Bb, nb + g4, kw,     lane4);
                        u32 b1 = ldf64w(Bb, nb + g4, kw + 4, lane4);
                        MMA(O[0][nf], a[0][0], a[0][1], a[0][2], a[0][3], b0, b1);
                        MMA(O[1][nf], a[1][0], a[1][1], a[1][2], a[1][3], b0, b1);
                    }
                }
            }
        }
    }

    // ---- epilogue ----
    if ((tid & 3) == 0) LI[tid >> 2] = 1.f / lrun;
    __syncthreads();
    #pragma unroll
    for (int mf = 0; mf < 2; mf++){
        int r0 = wm + mf*16 + g4, r1 = r0 + 8;
        float li0 = LI[r0], li1 = LI[r1];
        #pragma unroll
        for (int nf = 0; nf < 2; nf++){
            int c = wnp + nf*8 + lane4*2;
            *reinterpret_cast<float2*>(out + ((size_t)(i0 + r0) * BHN + bh) * DH + c)
                = make_float2(O[mf][nf][0] * li0, O[mf][nf][1] * li0);
            *reinterpret_cast<float2*>(out + ((size_t)(i0 + r1) * BHN + bh) * DH + c)
                = make_float2(O[mf][nf][2] * li1, O[mf][nf][3] * li1);
        }
    }
}

extern "C" void kernel_launch(void* const* d_in, const int* in_sizes, int n_in,
                              void* d_out, int out_size)
{
    const float* q   = (const float*)d_in[0];
    const float* k   = (const float*)d_in[1];
    const float* v   = (const float*)d_in[2];
    const float* emb = (const float*)d_in[3];
    float* out = (float*)d_out;

    cudaFuncSetAttribute(attn_mma512_kernel,
                         cudaFuncAttributeMaxDynamicSharedMemorySize, SM_TOTAL);
    dim3 grid(BHN, 512 / TQ);   // (256 bh, 4 q-tiles)
    attn_mma512_kernel<<<grid, THREADS, SM_TOTAL>>>(q, k, v, emb, out);
}

// round 17
// speedup vs baseline: 1.8158x; 1.8158x over previous
#include <cuda_runtime.h>
#include <cuda_bf16.h>
#include <cstdint>

typedef uint32_t u32;
typedef uint64_t u64;

#define BHN 256
#define NHEADS 16
#define DH 64
#define TQ 128
#define TK 128
#define THREADS 512

// ---- smem byte offsets (225 KB, 1 CTA/SM) ----
#define SM_QH 0        // Q hi 128x64 bf16 (16K), persists
#define SM_QL 16384
#define SM_GH 32768    // K@q-rows hi/lo (bias A), persists
#define SM_GL 49152
#define SM_KH 65536    // K tile hi (16K); aliased by V^T hi (64 d x 128 j) after QK
#define SM_KL 81920
#define SM_EH 98304    // E band 256 rows x 64 bf16 hi (32K)
#define SM_EL 131072
#define SM_SC 163840   // score f32 128x128 (64K); later Ph(32K)+Pl(32K)
#define SM_PH 163840
#define SM_PL 196608
#define SM_CR 229376   // corr[128] f32
#define SM_LI 229888   // linv[128] f32
#define SM_TOTAL 230400

__device__ __forceinline__ void MMA(float* c, u32 a0, u32 a1, u32 a2, u32 a3, u32 b0, u32 b1){
    asm volatile("mma.sync.aligned.m16n8k16.row.col.f32.bf16.bf16.f32 "
        "{%0,%1,%2,%3}, {%4,%5,%6,%7}, {%8,%9}, {%0,%1,%2,%3};"
        : "+f"(c[0]), "+f"(c[1]), "+f"(c[2]), "+f"(c[3])
        : "r"(a0), "r"(a1), "r"(a2), "r"(a3), "r"(b0), "r"(b1));
}

// fragment word load, 32-word rows (64 bf16)
__device__ __forceinline__ u32 ldf32w(const u32* buf, int row, int kw, int lane4){
    return buf[row*32 + ((kw + lane4) ^ ((row & 7) << 2))];
}
// fragment word load, 64-word rows (128 bf16) — P and V^T
__device__ __forceinline__ u32 ldf64w(const u32* buf, int row, int kw, int lane4){
    return buf[row*64 + ((kw + lane4) ^ ((row & 7) << 2))];
}
// score f32 word index (128-word rows, pair-swizzled)
__device__ __forceinline__ int sidx(int r, int c){
    return r*128 + 2*((c >> 1) ^ ((r & 7) << 2)) + (c & 1);
}

__device__ __forceinline__ void split2(float x0, float x1, u32 &H, u32 &L){
    __nv_bfloat162 hv = __floats2bfloat162_rn(x0, x1);
    __nv_bfloat162 lv = __floats2bfloat162_rn(x0 - __bfloat162float(hv.x),
                                              x1 - __bfloat162float(hv.y));
    H = *reinterpret_cast<u32*>(&hv);
    L = *reinterpret_cast<u32*>(&lv);
}
__device__ __forceinline__ void splitpack4(float4 a, u64 &H, u64 &L){
    u32 h0,l0,h1,l1;
    split2(a.x, a.y, h0, l0);
    split2(a.z, a.w, h1, l1);
    H = (u64)h0 | ((u64)h1 << 32);
    L = (u64)l0 | ((u64)l1 << 32);
}
__device__ __forceinline__ void st_hl(u32* bufH, u32* bufL, int row, int sg, u64 Hv, u64 Lv){
    int w = row*32 + ((2*sg) ^ ((row & 7) << 2));
    *reinterpret_cast<u64*>(bufH + w) = Hv;
    *reinterpret_cast<u64*>(bufL + w) = Lv;
}

__global__ void __launch_bounds__(THREADS, 1)
attn_mma512b_kernel(const float* __restrict__ q, const float* __restrict__ k,
                    const float* __restrict__ v, const float* __restrict__ emb,
                    float* __restrict__ out)
{
    extern __shared__ char smc[];
    u32* QH = (u32*)(smc + SM_QH);  u32* QL = (u32*)(smc + SM_QL);
    u32* GH = (u32*)(smc + SM_GH);  u32* GL = (u32*)(smc + SM_GL);
    u32* KH = (u32*)(smc + SM_KH);  u32* KL = (u32*)(smc + SM_KL);   // also V^T
    u32* EH = (u32*)(smc + SM_EH);  u32* EL = (u32*)(smc + SM_EL);
    u32* PH = (u32*)(smc + SM_PH);  u32* PL = (u32*)(smc + SM_PL);
    float* SC = (float*)(smc + SM_SC);
    float* CR = (float*)(smc + SM_CR);
    float* LI = (float*)(smc + SM_LI);

    const int tid = threadIdx.x;
    const int T = tid & 31, W = tid >> 5;        // 16 warps
    const int lane4 = T & 3, g4 = T >> 2;
    const int wm  = (W >> 2) * 32;               // 4 m-groups of 32 rows
    const int wnq = (W & 3) * 32;                // QK cols (128 wide)
    const int wub = (W & 3) * 64;                // band u cols (256 wide)
    const int wnp = (W & 3) * 16;                // PV cols (64 wide)
    const int bh = blockIdx.x, h = bh & (NHEADS - 1);
    const int i0 = blockIdx.y * TQ;
    const float scale = 0.125f;

    // ---- prologue: load+split Q and K@q-rows ----
    #pragma unroll
    for (int it = 0; it < 4; it++){
        int idx = tid + THREADS*it;
        int row = idx >> 4, sg = idx & 15;
        size_t g = ((size_t)(i0 + row) * BHN + bh) * DH + sg * 4;
        float4 qa = *(const float4*)(q + g);
        float4 ka = *(const float4*)(k + g);
        u64 H, L;
        splitpack4(qa, H, L); st_hl(QH, QL, row, sg, H, L);
        splitpack4(ka, H, L); st_hl(GH, GL, row, sg, H, L);
    }

    float O[2][2][4];
    #pragma unroll
    for (int a = 0; a < 2; a++)
        #pragma unroll
        for (int b = 0; b < 2; b++)
            #pragma unroll
            for (int c = 0; c < 4; c++) O[a][b][c] = 0.f;
    float mrun = -1e30f, lrun = 0.f;

    #pragma unroll 1
    for (int t = 0; t < 4; t++){
        const int j0 = t * TK;
        __syncthreads();   // prev PV done with V^T (K alias) and P

        // ---- load K tile + full E band (256 rows, row 255 zero/guarded) ----
        #pragma unroll
        for (int it = 0; it < 4; it++){
            int idx = tid + THREADS*it;
            int row = idx >> 4, sg = idx & 15;
            size_t g = ((size_t)(j0 + row) * BHN + bh) * DH + sg * 4;
            float4 ka = *(const float4*)(k + g);
            u64 H, L; splitpack4(ka, H, L);
            st_hl(KH, KL, row, sg, H, L);
        }
        {
            int rb = j0 - i0 + 384;               // in [0,768]
            #pragma unroll
            for (int it = 0; it < 8; it++){
                int idx = tid + THREADS*it;
                int row = idx >> 4, sg = idx & 15;
                int gr = rb + row;
                u64 H = 0ull, L = 0ull;
                if (gr <= 1022){
                    float4 ea = *(const float4*)(emb + ((size_t)h*1023 + gr)*DH + sg*4);
                    splitpack4(ea, H, L);
                }
                st_hl(EH, EL, row, sg, H, L);
            }
        }
        __syncthreads();

        // ---- QK^T: 3 hi/lo splits -> SC ----
        {
            float C[2][4][4];
            #pragma unroll
            for (int a = 0; a < 2; a++)
                #pragma unroll
                for (int b = 0; b < 4; b++)
                    #pragma unroll
                    for (int c = 0; c < 4; c++) C[a][b][c] = 0.f;
            #pragma unroll
            for (int s = 0; s < 3; s++){
                const u32* Ab = (s == 2) ? QL : QH;
                const u32* Bb = (s == 1) ? KL : KH;
                #pragma unroll
                for (int ks = 0; ks < 4; ks++){
                    int kw = ks * 8;
                    u32 a[2][4];
                    #pragma unroll
                    for (int mf = 0; mf < 2; mf++){
                        int rb2 = wm + mf*16;
                        a[mf][0] = ldf32w(Ab, rb2 + g4,     kw,     lane4);
                        a[mf][1] = ldf32w(Ab, rb2 + 8 + g4, kw,     lane4);
                        a[mf][2] = ldf32w(Ab, rb2 + g4,     kw + 4, lane4);
                        a[mf][3] = ldf32w(Ab, rb2 + 8 + g4, kw + 4, lane4);
                    }
                    #pragma unroll
                    for (int nf = 0; nf < 4; nf++){
                        int nb = wnq + nf*8;
                        u32 b0 = ldf32w(Bb, nb + g4, kw,     lane4);
                        u32 b1 = ldf32w(Bb, nb + g4, kw + 4, lane4);
                        MMA(C[0][nf], a[0][0], a[0][1], a[0][2], a[0][3], b0, b1);
                        MMA(C[1][nf], a[1][0], a[1][1], a[1][2], a[1][3], b0, b1);
                    }
                }
            }
            #pragma unroll
            for (int mf = 0; mf < 2; mf++)
                #pragma unroll
                for (int nf = 0; nf < 4; nf++){
                    int r = wm + mf*16 + g4;
                    int c = wnq + nf*8 + lane4*2;
                    *reinterpret_cast<float2*>(SC + sidx(r, c))     = make_float2(C[mf][nf][0], C[mf][nf][1]);
                    *reinterpret_cast<float2*>(SC + sidx(r + 8, c)) = make_float2(C[mf][nf][2], C[mf][nf][3]);
                }
        }
        __syncthreads();   // SC complete; K tile dead

        // ---- V^T build into dead K space, then band in TWO 32-ucol chunks ----
        {
            #pragma unroll
            for (int it = 0; it < 2; it++){
                int idx = tid + THREADS*it;
                int jp = idx & 63, ds = idx >> 6;     // 64 j-pairs, 16 d-segs
                union { float4 v4; float f[4]; } A2, B2;
                A2.v4 = *(const float4*)(v + ((size_t)(j0 + 2*jp    ) * BHN + bh) * DH + 4*ds);
                B2.v4 = *(const float4*)(v + ((size_t)(j0 + 2*jp + 1) * BHN + bh) * DH + 4*ds);
                #pragma unroll
                for (int e = 0; e < 4; e++){
                    int d = 4*ds + e;
                    u32 hi, lo; split2(A2.f[e], B2.f[e], hi, lo);
                    int wv = d*64 + (jp ^ ((d & 7) << 2));
                    KH[wv] = hi; KL[wv] = lo;
                }
            }

            // band: D'[i,u] = KQ.E, chunked so C stays at 32 regs (no spill)
            #pragma unroll 1
            for (int ch = 0; ch < 2; ch++){
                float C[2][4][4];
                #pragma unroll
                for (int a = 0; a < 2; a++)
                    #pragma unroll
                    for (int b = 0; b < 4; b++)
                        #pragma unroll
                        for (int c = 0; c < 4; c++) C[a][b][c] = 0.f;
                const int ub = wub + ch*32;
                #pragma unroll
                for (int s = 0; s < 3; s++){
                    const u32* Ab = (s == 2) ? GL : GH;
                    const u32* Bb = (s == 1) ? EL : EH;
                    #pragma unroll
                    for (int ks = 0; ks < 4; ks++){
                        int kw = ks * 8;
                        u32 a[2][4];
                        #pragma unroll
                        for (int mf = 0; mf < 2; mf++){
                            int rb2 = wm + mf*16;
                            a[mf][0] = ldf32w(Ab, rb2 + g4,     kw,     lane4);
                            a[mf][1] = ldf32w(Ab, rb2 + 8 + g4, kw,     lane4);
                            a[mf][2] = ldf32w(Ab, rb2 + g4,     kw + 4, lane4);
                            a[mf][3] = ldf32w(Ab, rb2 + 8 + g4, kw + 4, lane4);
                        }
                        #pragma unroll
                        for (int nf = 0; nf < 4; nf++){
                            int nb = ub + nf*8;
                            u32 b0 = ldf32w(Bb, nb + g4, kw,     lane4);
                            u32 b1 = ldf32w(Bb, nb + g4, kw + 4, lane4);
                            MMA(C[0][nf], a[0][0], a[0][1], a[0][2], a[0][3], b0, b1);
                            MMA(C[1][nf], a[1][0], a[1][1], a[1][2], a[1][3], b0, b1);
                        }
                    }
                }
                // shear-add: score[r][u + r - 127] += C  (bijective -> no races)
                #pragma unroll
                for (int mf = 0; mf < 2; mf++)
                    #pragma unroll
                    for (int nf = 0; nf < 4; nf++){
                        int r0 = wm + mf*16 + g4, r1 = r0 + 8;
                        int u  = ub + nf*8 + lane4*2;
                        int ja = u + r0 - 127;
                        int jb = u + r1 - 127;
                        if ((unsigned)ja     < 128u) SC[sidx(r0, ja)]     += C[mf][nf][0];
                        if ((unsigned)(ja+1) < 128u) SC[sidx(r0, ja + 1)] += C[mf][nf][1];
                        if ((unsigned)jb     < 128u) SC[sidx(r1, jb)]     += C[mf][nf][2];
                        if ((unsigned)(jb+1) < 128u) SC[sidx(r1, jb + 1)] += C[mf][nf][3];
                    }
            }
        }
        __syncthreads();   // scores final; V^T ready

        // ---- softmax: 4 threads/row, qt-interleaved cols (conflict-free) ----
        {
            int r = tid >> 2, qt = tid & 3;
            float sv[32];
            #pragma unroll
            for (int p = 0; p < 16; p++){
                float2 t2 = *reinterpret_cast<float2*>(
                    SC + r*128 + 2*((4*p + qt) ^ ((r & 7) << 2)));
                sv[2*p] = t2.x; sv[2*p+1] = t2.y;
            }
            float rm = sv[0];
            #pragma unroll
            for (int e = 1; e < 32; e++) rm = fmaxf(rm, sv[e]);
            rm = fmaxf(rm, __shfl_xor_sync(0xffffffffu, rm, 1));
            rm = fmaxf(rm, __shfl_xor_sync(0xffffffffu, rm, 2));
            float mn = fmaxf(mrun, rm * scale);
            float corr = __expf(mrun - mn);
            mrun = mn;
            float rs = 0.f;
            #pragma unroll
            for (int e = 0; e < 32; e++){ sv[e] = __expf(sv[e]*scale - mn); rs += sv[e]; }
            rs += __shfl_xor_sync(0xffffffffu, rs, 1);
            rs += __shfl_xor_sync(0xffffffffu, rs, 2);
            lrun = lrun * corr + rs;
            if (qt == 0) CR[r] = corr;
            __syncthreads();   // all SC reads done; safe to overwrite with P
            #pragma unroll
            for (int p = 0; p < 16; p++){
                u32 hi, lo; split2(sv[2*p], sv[2*p+1], hi, lo);
                int wv = r*64 + ((4*p + qt) ^ ((r & 7) << 2));
                PH[wv] = hi; PL[wv] = lo;
            }
        }
        __syncthreads();   // P ready

        // ---- PV: O = O*corr + P . V ----
        {
            float cr0[2], cr1[2];
            #pragma unroll
            for (int mf = 0; mf < 2; mf++){
                cr0[mf] = CR[wm + mf*16 + g4];
                cr1[mf] = CR[wm + mf*16 + 8 + g4];
            }
            #pragma unroll
            for (int mf = 0; mf < 2; mf++)
                #pragma unroll
                for (int nf = 0; nf < 2; nf++){
                    O[mf][nf][0] *= cr0[mf]; O[mf][nf][1] *= cr0[mf];
                    O[mf][nf][2] *= cr1[mf]; O[mf][nf][3] *= cr1[mf];
                }
            #pragma unroll
            for (int s = 0; s < 3; s++){
                const u32* Ab = (s == 2) ? PL : PH;
                const u32* Bb = (s == 1) ? KL : KH;   // V^T lo / hi
                #pragma unroll
                for (int ks = 0; ks < 8; ks++){
                    int kw = ks * 8;
                    u32 a[2][4];
                    #pragma unroll
                    for (int mf = 0; mf < 2; mf++){
                        int rb2 = wm + mf*16;
                        a[mf][0] = ldf64w(Ab, rb2 + g4,     kw,     lane4);
                        a[mf][1] = ldf64w(Ab, rb2 + 8 + g4, kw,     lane4);
                        a[mf][2] = ldf64w(Ab, rb2 + g4,     kw + 4, lane4);
                        a[mf][3] = ldf64w(Ab, rb2 + 8 + g4, kw + 4, lane4);
                    }
                    #pragma unroll
                    for (int nf = 0; nf < 2; nf++){
                        int nb = wnp + nf*8;
                        u32 b0 = ldf64w(Bb, nb + g4, kw,     lane4);
                        u32 b1 = ldf64w(Bb, nb + g4, kw + 4, lane4);
                        MMA(O[0][nf], a[0][0], a[0][1], a[0][2], a[0][3], b0, b1);
                        MMA(O[1][nf], a[1][0], a[1][1], a[1][2], a[1][3], b0, b1);
                    }
                }
            }
        }
    }

    // ---- epilogue ----
    if ((tid & 3) == 0) LI[tid >> 2] = 1.f / lrun;
    __syncthreads();
    #pragma unroll
    for (int mf = 0; mf < 2; mf++){
        int r0 = wm + mf*16 + g4, r1 = r0 + 8;
        float li0 = LI[r0], li1 = LI[r1];
        #pragma unroll
        for (int nf = 0; nf < 2; nf++){
            int c = wnp + nf*8 + lane4*2;
            *reinterpret_cast<float2*>(out + ((size_t)(i0 + r0) * BHN + bh) * DH + c)
                = make_float2(O[mf][nf][0] * li0, O[mf][nf][1] * li0);
            *reinterpret_cast<float2*>(out + ((size_t)(i0 + r1) * BHN + bh) * DH + c)
                = make_float2(O[mf][nf][2] * li1, O[mf][nf][3] * li1);
        }
    }
}

extern "C" void kernel_launch(void* const* d_in, const int* in_sizes, int n_in,
                              void* d_out, int out_size)
{
    const float* q   = (const float*)d_in[0];
    const float* k   = (const float*)d_in[1];
    const float* v   = (const float*)d_in[2];
    const float* emb = (const float*)d_in[3];
    float* out = (float*)d_out;

    cudaFuncSetAttribute(attn_mma512b_kernel,
                         cudaFuncAttributeMaxDynamicSharedMemorySize, SM_TOTAL);
    dim3 grid(BHN, 512 / TQ);   // (256 bh, 4 q-tiles)
    attn_mma512b_kernel<<<grid, THREADS, SM_TOTAL>>>(q, k, v, emb, out);
}